// round 6
// baseline (speedup 1.0000x reference)
#include <cuda_runtime.h>
#include <cstdint>

#define NPTS   256
#define NHEAD  8
#define HID    64
#define TPB    128
#define WARPS  4
#define TILES  2            // 32-pixel tiles per warp
#define CTA_PIX (WARPS * TILES * 32)   // 256

#define ROW_STRIDE 48       // bytes per staged pixel row (conflict-free for ldmatrix)
#define PLANE_BYTES (32 * ROW_STRIDE)
#define WARP_SMEM   (2 * PLANE_BYTES)  // hi + lo planes

__device__ __forceinline__ uint32_t smem_u32(const void* p) {
    uint32_t a;
    asm("{ .reg .u64 t; cvta.to.shared.u64 t, %1; cvt.u32.u64 %0, t; }" : "=r"(a) : "l"(p));
    return a;
}
__device__ __forceinline__ void ldm_x4(uint32_t* r, uint32_t addr) {
    asm volatile("ldmatrix.sync.aligned.m8n8.x4.shared.b16 {%0,%1,%2,%3}, [%4];"
                 : "=r"(r[0]), "=r"(r[1]), "=r"(r[2]), "=r"(r[3]) : "r"(addr));
}
__device__ __forceinline__ void mma_bf16(float* d, const uint32_t* a, const uint32_t* b) {
    asm volatile("mma.sync.aligned.m16n8k16.row.col.f32.bf16.bf16.f32 "
                 "{%0,%1,%2,%3}, {%4,%5,%6,%7}, {%8,%9}, {%0,%1,%2,%3};"
                 : "+f"(d[0]), "+f"(d[1]), "+f"(d[2]), "+f"(d[3])
                 : "r"(a[0]), "r"(a[1]), "r"(a[2]), "r"(a[3]), "r"(b[0]), "r"(b[1]));
}
// pack two f32 -> bf16x2 (v0 in LOW half), round-to-nearest
__device__ __forceinline__ uint32_t pack_rn(float v0, float v1) {
    uint32_t r;
    asm("cvt.rn.bf16x2.f32 %0, %1, %2;" : "=r"(r) : "f"(v1), "f"(v0));
    return r;
}
// hi = truncated bf16 pair (v0 low), lo = bf16_rn residual pair
__device__ __forceinline__ void split2(float v0, float v1, uint32_t& hi, uint32_t& lo) {
    uint32_t a = __float_as_uint(v0), b = __float_as_uint(v1);
    hi = __byte_perm(a, b, 0x7632);
    float l0 = v0 - __uint_as_float(a & 0xffff0000u);
    float l1 = v1 - __uint_as_float(b & 0xffff0000u);
    lo = pack_rn(l0, l1);
}

__device__ __forceinline__ float rcp_fast(float x) {
    float r;
    asm("rcp.approx.ftz.f32 %0, %1;" : "=f"(r) : "f"(x));
    return r;
}
__device__ __forceinline__ float ex2_fast(float x) {
    float r;
    asm("ex2.approx.ftz.f32 %0, %1;" : "=f"(r) : "f"(x));
    return r;
}

// SiLU on 4 values: 4x EX2 + 1x RCP (quad-reciprocal reconstruction).
// All f32; rcp.approx + mul roundings ~3e-7 rel.
__device__ __forceinline__ void silu4(float& v0, float& v1, float& v2, float& v3) {
    const float nL2E = -1.4426950408889634f;
    float u0 = ex2_fast(v0 * nL2E);
    float u1 = ex2_fast(v1 * nL2E);
    float u2 = ex2_fast(v2 * nL2E);
    float u3 = ex2_fast(v3 * nL2E);
    float d0 = 1.0f + u0, d1 = 1.0f + u1, d2 = 1.0f + u2, d3 = 1.0f + u3;
    float P = d0 * d1, Q = d2 * d3;
    float r = rcp_fast(P * Q);
    float rP = r * Q;           // 1/(d0*d1)
    float rQ = r * P;           // 1/(d2*d3)
    v0 = v0 * (rP * d1);
    v1 = v1 * (rP * d0);
    v2 = v2 * (rQ * d3);
    v3 = v3 * (rQ * d2);
}

__device__ __forceinline__ float silu_f(float x) {      // used in features only
    return __fdividef(x, 1.0f + __expf(-x));
}

__device__ __forceinline__ void compute_features(float4 f, float* o) {
    float rx = f.x, ry = f.y, rvx = f.z, rvy = f.w;
    float d2    = fmaf(rx, rx, ry * ry);
    float dist  = __fsqrt_rn(d2 + 1e-6f);
    float invde = __fdividef(1.0f, dist + 1e-6f);
    float invd  = __fdividef(1.0f, dist + 0.1f);
    float ssq   = fmaf(rvx, rvx, rvy * rvy);
    float rsp   = __fsqrt_rn(ssq + 1e-6f);
    float dot   = fmaf(rvx, rx, rvy * ry);
    float closing = dot * invde;
    float a    = -__fdividef(dot, ssq + 1e-6f);
    float e2a  = __expf(2.0f * a);
    float ttca = 1.0f - __fdividef(2.0f, e2a + 1.0f);
    o[0]  = rx;       o[1]  = ry;       o[2]  = rvx;      o[3]  = rvy;
    o[4]  = dist;     o[5]  = invd;     o[6]  = rsp;      o[7]  = closing;
    o[8]  = rx * invde; o[9] = ry * invde; o[10] = ttca;  o[11] = dot;
}

__global__ void __launch_bounds__(TPB, 4)
relfeat_hmma_kernel(const float* __restrict__ ff,
                    const float* __restrict__ W1,
                    const float* __restrict__ b1,
                    const float* __restrict__ W2,
                    const float* __restrict__ b2,
                    float* __restrict__ out) {
    __shared__ __align__(16) char stage[WARPS * WARP_SMEM];

    const int tid  = threadIdx.x;
    const int wid  = tid >> 5;
    const int lane = tid & 31;
    const int q    = lane & 3;        // quad col index
    const int g    = lane >> 2;       // row group

    const uint32_t hiBase = smem_u32(stage) + wid * WARP_SMEM;
    const uint32_t loBase = hiBase + PLANE_BYTES;

    // ---------- weights -> registers ----------
    // Layer1 B fragments: B1[k][n], k: 0..11 = W1 rows, 12 = b1, 13..15 = 0
    uint32_t w1hi[8][2], w1lo[8][2];
    #pragma unroll
    for (int t = 0; t < 8; t++) {
        int n = t * 8 + g;
        int k0 = 2 * q, k2 = 2 * q + 8;
        float v0 = W1[k0 * HID + n];
        float v1 = W1[(k0 + 1) * HID + n];
        float v2 = (k2 < 12) ? W1[k2 * HID + n] : (k2 == 12 ? b1[n] : 0.0f);
        float v3 = (k2 + 1 < 12) ? W1[(k2 + 1) * HID + n] : (k2 + 1 == 12 ? b1[n] : 0.0f);
        split2(v0, v1, w1hi[t][0], w1lo[t][0]);
        split2(v2, v3, w1hi[t][1], w1lo[t][1]);
    }
    // Layer2 B fragments: B2[k][o] = W2[k*8+o], k = 0..63
    uint32_t w2hi[4][2], w2lo[4][2];
    #pragma unroll
    for (int kt = 0; kt < 4; kt++) {
        int o = g;
        int k0 = 16 * kt + 2 * q;
        float v0 = W2[k0 * NHEAD + o];
        float v1 = W2[(k0 + 1) * NHEAD + o];
        float v2 = W2[(k0 + 8) * NHEAD + o];
        float v3 = W2[(k0 + 9) * NHEAD + o];
        split2(v0, v1, w2hi[kt][0], w2lo[kt][0]);
        split2(v2, v3, w2hi[kt][1], w2lo[kt][1]);
    }
    float b2a = b2[2 * q], b2b = b2[2 * q + 1];

    const int gw = blockIdx.x * WARPS + wid;   // global warp id
    const float4* ffp = reinterpret_cast<const float4*>(ff);

    // ldmatrix row address for this lane (within a 16-row mtile)
    const int lt = lane >> 3, lr = lane & 7;
    const uint32_t ldmOff = (uint32_t)(((lt & 1) * 8 + lr) * ROW_STRIDE + (lt >> 1) * 16);

    #pragma unroll 1
    for (int it = 0; it < TILES; it++) {
        const int pixBase = gw * (TILES * 32) + it * 32;

        // ---- features for this lane's pixel -> hi/lo bf16 rows in SMEM ----
        {
            float4 raw = ffp[pixBase + lane];
            float f[12];
            compute_features(raw, f);
            uint32_t hi8[8], lo8[8];
            #pragma unroll
            for (int c = 0; c < 6; c++) split2(f[2 * c], f[2 * c + 1], hi8[c], lo8[c]);
            hi8[6] = 0x00003F80u; lo8[6] = 0;   // k=12: 1.0 (bias lane), k=13: 0
            hi8[7] = 0;           lo8[7] = 0;   // k=14,15
            __syncwarp();
            uint32_t rowOff = wid * WARP_SMEM + (uint32_t)lane * ROW_STRIDE;
            *reinterpret_cast<uint4*>(stage + rowOff)                      = make_uint4(hi8[0], hi8[1], hi8[2], hi8[3]);
            *reinterpret_cast<uint4*>(stage + rowOff + 16)                 = make_uint4(hi8[4], hi8[5], hi8[6], hi8[7]);
            *reinterpret_cast<uint4*>(stage + rowOff + PLANE_BYTES)        = make_uint4(lo8[0], lo8[1], lo8[2], lo8[3]);
            *reinterpret_cast<uint4*>(stage + rowOff + PLANE_BYTES + 16)   = make_uint4(lo8[4], lo8[5], lo8[6], lo8[7]);
            __syncwarp();
        }

        #pragma unroll
        for (int mt = 0; mt < 2; mt++) {
            // ---- A fragments via ldmatrix ----
            uint32_t ahi[4], alo[4];
            ldm_x4(ahi, hiBase + (uint32_t)(mt * 16 * ROW_STRIDE) + ldmOff);
            ldm_x4(alo, loBase + (uint32_t)(mt * 16 * ROW_STRIDE) + ldmOff);

            // ---- layer1: D1 = A*B1 (3-product split) ----
            float d[8][4];
            #pragma unroll
            for (int t = 0; t < 8; t++) {
                d[t][0] = d[t][1] = d[t][2] = d[t][3] = 0.0f;
                mma_bf16(d[t], ahi, w1hi[t]);
                mma_bf16(d[t], ahi, w1lo[t]);
                mma_bf16(d[t], alo, w1hi[t]);
            }
            // ---- SiLU in-register (quad-rcp: 1.25 XU/value) ----
            #pragma unroll
            for (int t = 0; t < 8; t++)
                silu4(d[t][0], d[t][1], d[t][2], d[t][3]);

            // ---- layer2: accum layout == A-frag layout; split & MMA ----
            float dd[4] = {0.0f, 0.0f, 0.0f, 0.0f};
            #pragma unroll
            for (int kt = 0; kt < 4; kt++) {
                uint32_t a2hi[4], a2lo[4];
                split2(d[2 * kt][0],     d[2 * kt][1],     a2hi[0], a2lo[0]);
                split2(d[2 * kt][2],     d[2 * kt][3],     a2hi[1], a2lo[1]);
                split2(d[2 * kt + 1][0], d[2 * kt + 1][1], a2hi[2], a2lo[2]);
                split2(d[2 * kt + 1][2], d[2 * kt + 1][3], a2hi[3], a2lo[3]);
                mma_bf16(dd, a2hi, w2hi[kt]);
                mma_bf16(dd, a2hi, w2lo[kt]);
                mma_bf16(dd, a2lo, w2hi[kt]);
            }
            // ---- store transposed (B, H, N, N) ----
            int p0 = pixBase + mt * 16;
            int m = p0 & (NPTS - 1);
            int n = (p0 >> 8) & (NPTS - 1);
            int b = p0 >> 16;
            int base = b * (NHEAD * NPTS * NPTS) + n * NPTS + m;
            int c0 = (2 * q) * (NPTS * NPTS), c1 = (2 * q + 1) * (NPTS * NPTS);
            out[base + c0 + g]     = dd[0] + b2a;
            out[base + c1 + g]     = dd[1] + b2b;
            out[base + c0 + g + 8] = dd[2] + b2a;
            out[base + c1 + g + 8] = dd[3] + b2b;
        }
    }
}

extern "C" void kernel_launch(void* const* d_in, const int* in_sizes, int n_in,
                              void* d_out, int out_size) {
    const float* ff = (const float*)d_in[0];
    const float* W1 = (const float*)d_in[1];
    const float* b1 = (const float*)d_in[2];
    const float* W2 = (const float*)d_in[3];
    const float* b2 = (const float*)d_in[4];
    float* out = (float*)d_out;

    int pixels = out_size / NHEAD;        // 1,048,576
    int blocks = pixels / CTA_PIX;        // 4096
    relfeat_hmma_kernel<<<blocks, TPB>>>(ff, W1, b1, W2, b2, out);
}

// round 7
// speedup vs baseline: 1.9789x; 1.9789x over previous
#include <cuda_runtime.h>
#include <cuda_fp16.h>
#include <cstdint>

#define NPTS   256
#define NHEAD  8
#define HID    64
#define TPB    128
#define WARPS  4
#define TILES  4            // 32-pixel tiles per warp
#define CTA_PIX (WARPS * TILES * 32)   // 512

#define ROW_STRIDE 48       // bytes per staged pixel row (conflict-free ldmatrix phases)
#define WARP_SMEM  (32 * ROW_STRIDE)   // single fp16 plane

__device__ __forceinline__ uint32_t smem_u32(const void* p) {
    uint32_t a;
    asm("{ .reg .u64 t; cvta.to.shared.u64 t, %1; cvt.u32.u64 %0, t; }" : "=r"(a) : "l"(p));
    return a;
}
__device__ __forceinline__ void ldm_x4(uint32_t* r, uint32_t addr) {
    asm volatile("ldmatrix.sync.aligned.m8n8.x4.shared.b16 {%0,%1,%2,%3}, [%4];"
                 : "=r"(r[0]), "=r"(r[1]), "=r"(r[2]), "=r"(r[3]) : "r"(addr));
}
__device__ __forceinline__ void mma_f16(float* d, const uint32_t* a, const uint32_t* b) {
    asm volatile("mma.sync.aligned.m16n8k16.row.col.f32.f16.f16.f32 "
                 "{%0,%1,%2,%3}, {%4,%5,%6,%7}, {%8,%9}, {%0,%1,%2,%3};"
                 : "+f"(d[0]), "+f"(d[1]), "+f"(d[2]), "+f"(d[3])
                 : "r"(a[0]), "r"(a[1]), "r"(a[2]), "r"(a[3]), "r"(b[0]), "r"(b[1]));
}
__device__ __forceinline__ uint32_t h2(float lo, float hi) {   // lo -> low half
    uint32_t r;
    asm("cvt.rn.f16x2.f32 %0, %1, %2;" : "=r"(r) : "f"(hi), "f"(lo));
    return r;
}
__device__ __forceinline__ float tanh_fast(float x) {
    float r; asm("tanh.approx.f32 %0, %1;" : "=f"(r) : "f"(x)); return r;
}
__device__ __forceinline__ float sqrt_fast(float x) {
    float r; asm("sqrt.approx.ftz.f32 %0, %1;" : "=f"(r) : "f"(x)); return r;
}
__device__ __forceinline__ float rcp_fast(float x) {
    float r; asm("rcp.approx.ftz.f32 %0, %1;" : "=f"(r) : "f"(x)); return r;
}
// silu(x) = 0.5x*(1 + tanh(x/2)) : 2 FMA + 1 MUFU
__device__ __forceinline__ float silu_f(float x) {
    float hx = 0.5f * x;
    return fmaf(hx, tanh_fast(hx), hx);
}

__device__ __forceinline__ void compute_features(float4 f, float* o) {
    float rx = f.x, ry = f.y, rvx = f.z, rvy = f.w;
    float d2    = fmaf(rx, rx, ry * ry);
    float dist  = sqrt_fast(d2 + 1e-6f);
    float invde = rcp_fast(dist + 1e-6f);
    float invd  = rcp_fast(dist + 0.1f);
    float ssq   = fmaf(rvx, rvx, rvy * rvy);
    float rsp   = sqrt_fast(ssq + 1e-6f);
    float dot   = fmaf(rvx, rx, rvy * ry);
    float closing = dot * invde;
    float ttca  = tanh_fast(-dot * rcp_fast(ssq + 1e-6f));
    o[0]  = rx;       o[1]  = ry;       o[2]  = rvx;      o[3]  = rvy;
    o[4]  = dist;     o[5]  = invd;     o[6]  = rsp;      o[7]  = closing;
    o[8]  = rx * invde; o[9] = ry * invde; o[10] = ttca;  o[11] = dot;
}

__global__ void __launch_bounds__(TPB, 5)
relfeat_hmma_kernel(const float* __restrict__ ff,
                    const float* __restrict__ W1,
                    const float* __restrict__ b1,
                    const float* __restrict__ W2,
                    const float* __restrict__ b2,
                    float* __restrict__ out) {
    __shared__ __align__(16) char stage[WARPS * WARP_SMEM];

    const int tid  = threadIdx.x;
    const int wid  = tid >> 5;
    const int lane = tid & 31;
    const int q    = lane & 3;        // quad col index
    const int g    = lane >> 2;       // row group

    const uint32_t warpBase = smem_u32(stage) + wid * WARP_SMEM;

    // ---------- weights -> fp16 register fragments ----------
    // Layer1 B: B1[k][n], k: 0..11 = W1 rows, 12 = b1, 13..15 = 0
    uint32_t w1[8][2];
    #pragma unroll
    for (int t = 0; t < 8; t++) {
        int n = t * 8 + g;
        int k0 = 2 * q, k2 = 2 * q + 8;
        float v0 = W1[k0 * HID + n];
        float v1 = W1[(k0 + 1) * HID + n];
        float v2 = (k2 < 12) ? W1[k2 * HID + n] : (k2 == 12 ? b1[n] : 0.0f);
        float v3 = (k2 + 1 < 12) ? W1[(k2 + 1) * HID + n] : 0.0f;
        w1[t][0] = h2(v0, v1);
        w1[t][1] = h2(v2, v3);
    }
    // Layer2 B: B2[k][o] = W2[k*8+o]
    uint32_t w2[4][2];
    #pragma unroll
    for (int kt = 0; kt < 4; kt++) {
        int o = g;
        int k0 = 16 * kt + 2 * q;
        w2[kt][0] = h2(W2[k0 * NHEAD + o],       W2[(k0 + 1) * NHEAD + o]);
        w2[kt][1] = h2(W2[(k0 + 8) * NHEAD + o], W2[(k0 + 9) * NHEAD + o]);
    }
    const float b2a = b2[2 * q], b2b = b2[2 * q + 1];

    const int gw = blockIdx.x * WARPS + wid;   // global warp id
    const float4* ffp = reinterpret_cast<const float4*>(ff);

    // ldmatrix row address for this lane (within a 16-row mtile)
    const int lt = lane >> 3, lr = lane & 7;
    const uint32_t ldmOff = (uint32_t)(((lt & 1) * 8 + lr) * ROW_STRIDE + (lt >> 1) * 16);

    #pragma unroll 1
    for (int it = 0; it < TILES; it++) {
        const int pixBase = gw * (TILES * 32) + it * 32;

        // ---- features for this lane's pixel -> 16 fp16 per row in SMEM ----
        {
            float4 raw = ffp[pixBase + lane];
            float f[12];
            compute_features(raw, f);
            uint32_t h8[8];
            #pragma unroll
            for (int c = 0; c < 6; c++) h8[c] = h2(f[2 * c], f[2 * c + 1]);
            h8[6] = 0x00003C00u;   // k=12: fp16 1.0 (bias lane), k=13: 0
            h8[7] = 0;             // k=14,15
            __syncwarp();
            char* row = stage + wid * WARP_SMEM + lane * ROW_STRIDE;
            *reinterpret_cast<uint4*>(row)      = make_uint4(h8[0], h8[1], h8[2], h8[3]);
            *reinterpret_cast<uint4*>(row + 16) = make_uint4(h8[4], h8[5], h8[6], h8[7]);
            __syncwarp();
        }

        #pragma unroll
        for (int mt = 0; mt < 2; mt++) {
            // ---- A fragment via ldmatrix ----
            uint32_t a[4];
            ldm_x4(a, warpBase + (uint32_t)(mt * 16 * ROW_STRIDE) + ldmOff);

            // ---- layer1: D1 = A*B1, 8 independent n-tiles ----
            float d[8][4];
            #pragma unroll
            for (int t = 0; t < 8; t++) {
                d[t][0] = d[t][1] = d[t][2] = d[t][3] = 0.0f;
                mma_f16(d[t], a, w1[t]);
            }
            // ---- SiLU in-register ----
            #pragma unroll
            for (int t = 0; t < 8; t++) {
                d[t][0] = silu_f(d[t][0]); d[t][1] = silu_f(d[t][1]);
                d[t][2] = silu_f(d[t][2]); d[t][3] = silu_f(d[t][3]);
            }
            // ---- layer2: accum layout == A-frag layout; cvt & MMA ----
            float dd0[4] = {b2a, b2b, b2a, b2b};   // b2 folded into init
            float dd1[4] = {0.0f, 0.0f, 0.0f, 0.0f};
            #pragma unroll
            for (int kt = 0; kt < 4; kt++) {
                uint32_t a2[4];
                a2[0] = h2(d[2 * kt][0],     d[2 * kt][1]);
                a2[1] = h2(d[2 * kt][2],     d[2 * kt][3]);
                a2[2] = h2(d[2 * kt + 1][0], d[2 * kt + 1][1]);
                a2[3] = h2(d[2 * kt + 1][2], d[2 * kt + 1][3]);
                mma_f16((kt & 1) ? dd1 : dd0, a2, w2[kt]);
            }
            // ---- store transposed (B, H, N, N) ----
            int p0 = pixBase + mt * 16;
            int m = p0 & (NPTS - 1);
            int n = (p0 >> 8) & (NPTS - 1);
            int b = p0 >> 16;
            int base = b * (NHEAD * NPTS * NPTS) + n * NPTS + m;
            int c0 = (2 * q) * (NPTS * NPTS), c1 = (2 * q + 1) * (NPTS * NPTS);
            out[base + c0 + g]     = dd0[0] + dd1[0];
            out[base + c1 + g]     = dd0[1] + dd1[1];
            out[base + c0 + g + 8] = dd0[2] + dd1[2];
            out[base + c1 + g + 8] = dd0[3] + dd1[3];
        }
    }
}

extern "C" void kernel_launch(void* const* d_in, const int* in_sizes, int n_in,
                              void* d_out, int out_size) {
    const float* ff = (const float*)d_in[0];
    const float* W1 = (const float*)d_in[1];
    const float* b1 = (const float*)d_in[2];
    const float* W2 = (const float*)d_in[3];
    const float* b2 = (const float*)d_in[4];
    float* out = (float*)d_out;

    int pixels = out_size / NHEAD;        // 1,048,576
    int blocks = pixels / CTA_PIX;        // 2048
    relfeat_hmma_kernel<<<blocks, TPB>>>(ff, W1, b1, W2, b2, out);
}

// round 8
// speedup vs baseline: 1.9929x; 1.0071x over previous
#include <cuda_runtime.h>
#include <cuda_fp16.h>
#include <cstdint>

#define NPTS   256
#define NHEAD  8
#define HID    64
#define TPB    128
#define WARPS  4
#define TILES  4            // 32-pixel tiles per warp
#define CTA_PIX (WARPS * TILES * 32)   // 512

#define ROW_STRIDE 48       // bytes per staged pixel row (conflict-free ldmatrix phases)
#define WARP_SMEM  (32 * ROW_STRIDE)   // single fp16 plane

__device__ __forceinline__ uint32_t smem_u32(const void* p) {
    uint32_t a;
    asm("{ .reg .u64 t; cvta.to.shared.u64 t, %1; cvt.u32.u64 %0, t; }" : "=r"(a) : "l"(p));
    return a;
}
__device__ __forceinline__ void ldm_x4(uint32_t* r, uint32_t addr) {
    asm volatile("ldmatrix.sync.aligned.m8n8.x4.shared.b16 {%0,%1,%2,%3}, [%4];"
                 : "=r"(r[0]), "=r"(r[1]), "=r"(r[2]), "=r"(r[3]) : "r"(addr));
}
__device__ __forceinline__ void mma_f16(float* d, const uint32_t* a, const uint32_t* b) {
    asm volatile("mma.sync.aligned.m16n8k16.row.col.f32.f16.f16.f32 "
                 "{%0,%1,%2,%3}, {%4,%5,%6,%7}, {%8,%9}, {%0,%1,%2,%3};"
                 : "+f"(d[0]), "+f"(d[1]), "+f"(d[2]), "+f"(d[3])
                 : "r"(a[0]), "r"(a[1]), "r"(a[2]), "r"(a[3]), "r"(b[0]), "r"(b[1]));
}
__device__ __forceinline__ uint32_t h2(float lo, float hi) {   // lo -> low half
    uint32_t r;
    asm("cvt.rn.f16x2.f32 %0, %1, %2;" : "=r"(r) : "f"(hi), "f"(lo));
    return r;
}
__device__ __forceinline__ float tanh_fast(float x) {
    float r; asm("tanh.approx.f32 %0, %1;" : "=f"(r) : "f"(x)); return r;
}
__device__ __forceinline__ float sqrt_fast(float x) {
    float r; asm("sqrt.approx.ftz.f32 %0, %1;" : "=f"(r) : "f"(x)); return r;
}
__device__ __forceinline__ float rcp_fast(float x) {
    float r; asm("rcp.approx.ftz.f32 %0, %1;" : "=f"(r) : "f"(x)); return r;
}
// silu(x) = 0.5x*(1 + tanh(x/2)) : 2 FMA + 1 MUFU
__device__ __forceinline__ float silu_f(float x) {
    float hx = 0.5f * x;
    return fmaf(hx, tanh_fast(hx), hx);
}

__device__ __forceinline__ void compute_features(float4 f, float* o) {
    float rx = f.x, ry = f.y, rvx = f.z, rvy = f.w;
    float d2    = fmaf(rx, rx, ry * ry);
    float dist  = sqrt_fast(d2 + 1e-6f);
    float invde = rcp_fast(dist + 1e-6f);
    float invd  = rcp_fast(dist + 0.1f);
    float ssq   = fmaf(rvx, rvx, rvy * rvy);
    float rsp   = sqrt_fast(ssq + 1e-6f);
    float dot   = fmaf(rvx, rx, rvy * ry);
    float closing = dot * invde;
    float ttca  = tanh_fast(-dot * rcp_fast(ssq + 1e-6f));
    o[0]  = rx;       o[1]  = ry;       o[2]  = rvx;      o[3]  = rvy;
    o[4]  = dist;     o[5]  = invd;     o[6]  = rsp;      o[7]  = closing;
    o[8]  = rx * invde; o[9] = ry * invde; o[10] = ttca;  o[11] = dot;
}

__global__ void __launch_bounds__(TPB, 6)
relfeat_hmma_kernel(const float* __restrict__ ff,
                    const float* __restrict__ W1,
                    const float* __restrict__ b1,
                    const float* __restrict__ W2,
                    const float* __restrict__ b2,
                    float* __restrict__ out) {
    __shared__ __align__(16) char stage[WARPS * WARP_SMEM];

    const int tid  = threadIdx.x;
    const int wid  = tid >> 5;
    const int lane = tid & 31;
    const int q    = lane & 3;        // quad col index
    const int g    = lane >> 2;       // row group

    const uint32_t warpBase = smem_u32(stage) + wid * WARP_SMEM;

    // ---------- weights -> fp16 register fragments ----------
    // Layer1 B: B1[k][n], k: 0..11 = W1 rows, 12 = b1, 13..15 = 0
    uint32_t w1[8][2];
    #pragma unroll
    for (int t = 0; t < 8; t++) {
        int n = t * 8 + g;
        int k0 = 2 * q, k2 = 2 * q + 8;
        float v0 = W1[k0 * HID + n];
        float v1 = W1[(k0 + 1) * HID + n];
        float v2 = (k2 < 12) ? W1[k2 * HID + n] : (k2 == 12 ? b1[n] : 0.0f);
        float v3 = (k2 + 1 < 12) ? W1[(k2 + 1) * HID + n] : 0.0f;
        w1[t][0] = h2(v0, v1);
        w1[t][1] = h2(v2, v3);
    }
    // Layer2 B: B2[k][o] = W2[k*8+o]
    uint32_t w2[4][2];
    #pragma unroll
    for (int kt = 0; kt < 4; kt++) {
        int o = g;
        int k0 = 16 * kt + 2 * q;
        w2[kt][0] = h2(W2[k0 * NHEAD + o],       W2[(k0 + 1) * NHEAD + o]);
        w2[kt][1] = h2(W2[(k0 + 8) * NHEAD + o], W2[(k0 + 9) * NHEAD + o]);
    }
    const float b2a = b2[2 * q], b2b = b2[2 * q + 1];

    const int gw = blockIdx.x * WARPS + wid;   // global warp id
    const float4* ffp = reinterpret_cast<const float4*>(ff);

    // ldmatrix row address for this lane (within a 16-row mtile)
    const int lt = lane >> 3, lr = lane & 7;
    const uint32_t ldmOff = (uint32_t)(((lt & 1) * 8 + lr) * ROW_STRIDE + (lt >> 1) * 16);

    #pragma unroll 1
    for (int it = 0; it < TILES; it++) {
        const int pixBase = gw * (TILES * 32) + it * 32;

        // ---- features for this lane's pixel -> 16 fp16 per row in SMEM ----
        {
            float4 raw = ffp[pixBase + lane];
            float f[12];
            compute_features(raw, f);
            uint32_t h8[8];
            #pragma unroll
            for (int c = 0; c < 6; c++) h8[c] = h2(f[2 * c], f[2 * c + 1]);
            h8[6] = 0x00003C00u;   // k=12: fp16 1.0 (bias lane), k=13: 0
            h8[7] = 0;             // k=14,15
            __syncwarp();
            char* row = stage + wid * WARP_SMEM + lane * ROW_STRIDE;
            *reinterpret_cast<uint4*>(row)      = make_uint4(h8[0], h8[1], h8[2], h8[3]);
            *reinterpret_cast<uint4*>(row + 16) = make_uint4(h8[4], h8[5], h8[6], h8[7]);
            __syncwarp();
        }

        #pragma unroll
        for (int mt = 0; mt < 2; mt++) {
            // ---- A fragment via ldmatrix ----
            uint32_t a[4];
            ldm_x4(a, warpBase + (uint32_t)(mt * 16 * ROW_STRIDE) + ldmOff);

            // ---- fused layer1 -> SiLU -> layer2, kt-blocked (8 f32 live) ----
            float dd0[4] = {b2a, b2b, b2a, b2b};   // b2 folded into init
            float dd1[4] = {0.0f, 0.0f, 0.0f, 0.0f};
            #pragma unroll
            for (int kt = 0; kt < 4; kt++) {
                float d0[4] = {0.0f, 0.0f, 0.0f, 0.0f};
                float d1[4] = {0.0f, 0.0f, 0.0f, 0.0f};
                mma_f16(d0, a, w1[2 * kt]);
                mma_f16(d1, a, w1[2 * kt + 1]);
                d0[0] = silu_f(d0[0]); d0[1] = silu_f(d0[1]);
                d0[2] = silu_f(d0[2]); d0[3] = silu_f(d0[3]);
                d1[0] = silu_f(d1[0]); d1[1] = silu_f(d1[1]);
                d1[2] = silu_f(d1[2]); d1[3] = silu_f(d1[3]);
                uint32_t a2[4];
                a2[0] = h2(d0[0], d0[1]);
                a2[1] = h2(d0[2], d0[3]);
                a2[2] = h2(d1[0], d1[1]);
                a2[3] = h2(d1[2], d1[3]);
                mma_f16((kt & 1) ? dd1 : dd0, a2, w2[kt]);
            }
            // ---- store transposed (B, H, N, N) ----
            int p0 = pixBase + mt * 16;
            int m = p0 & (NPTS - 1);
            int n = (p0 >> 8) & (NPTS - 1);
            int b = p0 >> 16;
            int base = b * (NHEAD * NPTS * NPTS) + n * NPTS + m;
            int c0 = (2 * q) * (NPTS * NPTS), c1 = (2 * q + 1) * (NPTS * NPTS);
            out[base + c0 + g]     = dd0[0] + dd1[0];
            out[base + c1 + g]     = dd0[1] + dd1[1];
            out[base + c0 + g + 8] = dd0[2] + dd1[2];
            out[base + c1 + g + 8] = dd0[3] + dd1[3];
        }
    }
}

extern "C" void kernel_launch(void* const* d_in, const int* in_sizes, int n_in,
                              void* d_out, int out_size) {
    const float* ff = (const float*)d_in[0];
    const float* W1 = (const float*)d_in[1];
    const float* b1 = (const float*)d_in[2];
    const float* W2 = (const float*)d_in[3];
    const float* b2 = (const float*)d_in[4];
    float* out = (float*)d_out;

    int pixels = out_size / NHEAD;        // 1,048,576
    int blocks = pixels / CTA_PIX;        // 2048
    relfeat_hmma_kernel<<<blocks, TPB>>>(ff, W1, b1, W2, b2, out);
}